// round 1
// baseline (speedup 1.0000x reference)
#include <cuda_runtime.h>

#define DH    256
#define NLAY  4
#define NGR   64
#define NGMAX 50000
#define BNEPS 1e-5f

// ---------------- scratch (static __device__ globals; no allocations) ----------------
__device__ float g_H [NGMAX*DH];
__device__ float g_T0[NGMAX*DH];
__device__ float g_T1[NGMAX*DH];
__device__ float g_stats[2*DH];
__device__ float g_scale[DH];
__device__ float g_shift[DH];
__device__ float g_read[2*NGR*DH];

// ---------------- small utility kernels ----------------
__global__ void zero_kernel(float* p, int n) {
    int i = blockIdx.x * blockDim.x + threadIdx.x;
    if (i < n) p[i] = 0.f;
}

// ---------------- fused GEMM: C = op_A(A) @ W + bias, optional column stats ----------------
// A: [M,K] row-major, W: [K,256] row-major, C: [M,256]
// TRANS_A: a = relu(a*scale[k] + shift[k]) applied while loading A (fuses previous BN+ReLU)
// stats (if non-null): atomically accumulates per-column sum / sumsq of C (for the next BN)
template<int K, bool TRANS_A>
__global__ __launch_bounds__(256) void gemm_k(
    const float* __restrict__ A, const float* __restrict__ W,
    const float* __restrict__ bias, float* __restrict__ C, int M,
    const float* __restrict__ scA, const float* __restrict__ shA,
    float* __restrict__ stats)
{
    __shared__ float As[16][68];           // padded (+4) to avoid STS conflicts, keeps 16B align
    __shared__ float Bs[16][64];
    __shared__ float red[2][16][64];

    const int tid = threadIdx.x;
    const int ty  = tid >> 4;              // 0..15  -> 4 rows
    const int tx  = tid & 15;              // 0..15  -> 4 cols
    const int mbase = blockIdx.x * 64;
    const int nbase = blockIdx.y * 64;

    float acc[4][4] = {};

    for (int kt = 0; kt < K; kt += 16) {
        {   // load A tile (transposed into As[k][row]) with optional BN+ReLU transform
            int kl = tid & 15;
            int k  = kt + kl;
            float sc = 0.f, sh = 0.f;
            if (TRANS_A) { sc = scA[k]; sh = shA[k]; }
            #pragma unroll
            for (int i = 0; i < 4; i++) {
                int rl = (tid >> 4) + i * 16;
                int r  = mbase + rl;
                float v = (r < M) ? A[(long)r * K + k] : 0.f;
                if (TRANS_A) v = fmaxf(fmaf(v, sc, sh), 0.f);
                As[kl][rl] = v;
            }
        }
        {   // load W tile
            int cl = tid & 63;
            int kb = tid >> 6;
            #pragma unroll
            for (int i = 0; i < 4; i++) {
                int kl = kb + i * 4;
                Bs[kl][cl] = W[(long)(kt + kl) * DH + nbase + cl];
            }
        }
        __syncthreads();
        #pragma unroll
        for (int k = 0; k < 16; k++) {
            float4 a4 = *(const float4*)&As[k][ty * 4];
            float4 b4 = *(const float4*)&Bs[k][tx * 4];
            float av[4] = {a4.x, a4.y, a4.z, a4.w};
            float bv[4] = {b4.x, b4.y, b4.z, b4.w};
            #pragma unroll
            for (int i = 0; i < 4; i++)
                #pragma unroll
                for (int j = 0; j < 4; j++)
                    acc[i][j] = fmaf(av[i], bv[j], acc[i][j]);
        }
        __syncthreads();
    }

    // epilogue: bias add, store, per-column partial stats
    const int col0 = nbase + tx * 4;
    float4 bv4 = *(const float4*)&bias[col0];
    const float bb[4] = {bv4.x, bv4.y, bv4.z, bv4.w};
    float s[4] = {}, q[4] = {};
    #pragma unroll
    for (int i = 0; i < 4; i++) {
        int r = mbase + ty * 4 + i;
        if (r < M) {
            float c0 = acc[i][0] + bb[0];
            float c1 = acc[i][1] + bb[1];
            float c2 = acc[i][2] + bb[2];
            float c3 = acc[i][3] + bb[3];
            float4 o = {c0, c1, c2, c3};
            *(float4*)&C[(long)r * DH + col0] = o;
            s[0] += c0; s[1] += c1; s[2] += c2; s[3] += c3;
            q[0] += c0*c0; q[1] += c1*c1; q[2] += c2*c2; q[3] += c3*c3;
        }
    }
    if (stats) {
        #pragma unroll
        for (int j = 0; j < 4; j++) { red[0][ty][tx*4+j] = s[j]; red[1][ty][tx*4+j] = q[j]; }
        __syncthreads();
        if (tid < 64) {
            float ss = 0.f, qq = 0.f;
            #pragma unroll
            for (int t = 0; t < 16; t++) { ss += red[0][t][tid]; qq += red[1][t][tid]; }
            atomicAdd(&stats[nbase + tid], ss);
            atomicAdd(&stats[DH + nbase + tid], qq);
        }
    }
}

// ---------------- BN finalize: stats -> (scale, shift); zero stats for reuse ----------------
__global__ void bn_finalize_k(const float* __restrict__ gamma, const float* __restrict__ beta,
                              float invN, float* stats, float* scale, float* shift) {
    int t = threadIdx.x;
    float m  = stats[t] * invN;
    float v  = stats[DH + t] * invN - m * m;
    float sc = gamma[t] * rsqrtf(v + BNEPS);
    scale[t] = sc;
    shift[t] = fmaf(-m, sc, beta[t]);
    stats[t] = 0.f; stats[DH + t] = 0.f;
}

// ---------------- aggregation ----------------
__global__ void init_agg_k(const float* __restrict__ H, float* __restrict__ out,
                           const float* __restrict__ eps, int l, int n4) {
    float e = 1.f + eps[l];
    int stride = gridDim.x * blockDim.x;
    for (int i = blockIdx.x * blockDim.x + threadIdx.x; i < n4; i += stride) {
        float4 v = ((const float4*)H)[i];
        v.x *= e; v.y *= e; v.z *= e; v.w *= e;
        ((float4*)out)[i] = v;
    }
}

__device__ __forceinline__ void red_add_v4(float* p, float4 v) {
    asm volatile("red.global.add.v4.f32 [%0], {%1,%2,%3,%4};"
                 :: "l"(p), "f"(v.x), "f"(v.y), "f"(v.z), "f"(v.w) : "memory");
}

// one warp per edge: out[dst] += H[src] (vectorized 16B reductions, 4x fewer L2 atomic ops)
__global__ __launch_bounds__(256) void scatter_k(
    const float* __restrict__ H, float* __restrict__ out,
    const int* __restrict__ src, const int* __restrict__ dst, int E)
{
    int w    = (blockIdx.x * blockDim.x + threadIdx.x) >> 5;
    int lane = threadIdx.x & 31;
    if (w >= E) return;
    int s = src[w], d = dst[w];
    const float4* hs = (const float4*)(H + (long)s * DH);
    float* od = out + (long)d * DH;
    float4 a = hs[lane * 2];
    float4 b = hs[lane * 2 + 1];
    red_add_v4(od + lane * 8,     a);
    red_add_v4(od + lane * 8 + 4, b);
}

// ---------------- elementwise BN stages ----------------
// Y = relu(X*scale + shift), accumulating column stats of Y (for the following BN)
__global__ void bnrelu_stats_k(const float* __restrict__ X, float* __restrict__ Y,
                               const float* __restrict__ scale, const float* __restrict__ shift,
                               int M, float* stats) {
    int c = threadIdx.x;
    float sc = scale[c], sh = shift[c];
    int rpb = (M + gridDim.x - 1) / gridDim.x;
    int r0 = blockIdx.x * rpb;
    int r1 = min(M, r0 + rpb);
    float s = 0.f, q = 0.f;
    for (int r = r0; r < r1; r++) {
        float v = fmaxf(fmaf(X[(long)r * DH + c], sc, sh), 0.f);
        Y[(long)r * DH + c] = v;
        s += v; q += v * v;
    }
    atomicAdd(&stats[c], s);
    atomicAdd(&stats[DH + c], q);
}

// H += relu(X*scale + shift)   (residual)
__global__ void bnrelu_resid_k(const float* __restrict__ X, float* __restrict__ H,
                               const float* __restrict__ scale, const float* __restrict__ shift,
                               int M) {
    int c = threadIdx.x;
    float sc = scale[c], sh = shift[c];
    int rpb = (M + gridDim.x - 1) / gridDim.x;
    int r0 = blockIdx.x * rpb;
    int r1 = min(M, r0 + rpb);
    for (int r = r0; r < r1; r++) {
        long idx = (long)r * DH + c;
        H[idx] += fmaxf(fmaf(X[idx], sc, sh), 0.f);
    }
}

// ---------------- readout: per-graph sum (gid is sorted -> run-length accumulate) ----------------
__global__ void readout_k(const float* __restrict__ H, const int* __restrict__ gid,
                          float* __restrict__ out, int M) {
    int c  = threadIdx.x;
    int r0 = blockIdx.x * 64;
    if (r0 >= M) return;
    int r1 = min(M, r0 + 64);
    int cur = gid[r0];
    float acc = 0.f;
    for (int r = r0; r < r1; r++) {
        int g = gid[r];
        if (g != cur) { atomicAdd(&out[cur * DH + c], acc); acc = 0.f; cur = g; }
        acc += H[(long)r * DH + c];
    }
    atomicAdd(&out[cur * DH + c], acc);
}

// ---------------- final predictor: y[g] = relu(|hg-hq| @ Wp1 + bp1) @ Wp2 + bp2 ----------------
__global__ void predictor_k(const float* __restrict__ rd, const float* __restrict__ Wp1,
                            const float* __restrict__ bp1, const float* __restrict__ Wp2,
                            const float* __restrict__ bp2, float* __restrict__ out) {
    __shared__ float dvec[DH];
    __shared__ float hred[DH];
    int g = blockIdx.x, t = threadIdx.x;
    dvec[t] = fabsf(rd[g * DH + t] - rd[NGR * DH + g * DH + t]);
    __syncthreads();
    float acc = bp1[t];
    for (int k = 0; k < DH; k++) acc = fmaf(dvec[k], Wp1[k * DH + t], acc);
    hred[t] = fmaxf(acc, 0.f) * Wp2[t];
    __syncthreads();
    for (int s = DH / 2; s > 0; s >>= 1) {
        if (t < s) hred[t] += hred[t + s];
        __syncthreads();
    }
    if (t == 0) out[g] = hred[0] + bp2[0];
}

// ---------------- host-side pipeline ----------------
static void process_graph(const float* X, const int* src, const int* dst, const int* gid,
                          int N, int E,
                          const float* W_emb, const float* b_emb, const float* eps,
                          const float* W1, const float* b1, const float* g1, const float* be1,
                          const float* W2, const float* b2, const float* gA, const float* beA,
                          const float* gG, const float* beG,
                          float* H, float* T0, float* T1,
                          float* stats, float* scale, float* shift, float* readout)
{
    dim3 gg((N + 63) / 64, 4);
    // node embedding (no BN after it)
    gemm_k<128, false><<<gg, 256>>>(X, W_emb, b_emb, H, N, nullptr, nullptr, nullptr);
    float invN = 1.f / (float)N;
    for (int l = 0; l < NLAY; l++) {
        // h = (1+eps)*H + segment_sum(H[src], dst)
        init_agg_k<<<1024, 256>>>(H, T0, eps, l, N * DH / 4);
        scatter_k<<<(E + 7) / 8, 256>>>(H, T0, src, dst, E);
        // h1 = h @ W1 + b1 (+ stats for bn1)
        gemm_k<256, false><<<gg, 256>>>(T0, W1 + l * DH * DH, b1 + l * DH, T1, N,
                                        nullptr, nullptr, stats);
        bn_finalize_k<<<1, DH>>>(g1 + l * DH, be1 + l * DH, invN, stats, scale, shift);
        // h2 = relu(bn1(h1)) @ W2 + b2 (BN+ReLU fused into A load; + stats for bnA)
        gemm_k<256, true><<<gg, 256>>>(T1, W2 + l * DH * DH, b2 + l * DH, T0, N,
                                       scale, shift, stats);
        bn_finalize_k<<<1, DH>>>(gA + l * DH, beA + l * DH, invN, stats, scale, shift);
        // t = relu(bnA(h2)) (+ stats for bnG)
        bnrelu_stats_k<<<512, DH>>>(T0, T1, scale, shift, N, stats);
        bn_finalize_k<<<1, DH>>>(gG + l * DH, beG + l * DH, invN, stats, scale, shift);
        // H = H_in + relu(bnG(t))
        bnrelu_resid_k<<<512, DH>>>(T1, H, scale, shift, N);
    }
    readout_k<<<(N + 63) / 64, 256>>>(H, gid, readout, N);
}

extern "C" void kernel_launch(void* const* d_in, const int* in_sizes, int n_in,
                              void* d_out, int out_size) {
    const float* X     = (const float*)d_in[0];
    const float* Xq    = (const float*)d_in[2];
    const float* W_emb = (const float*)d_in[4];
    const float* b_emb = (const float*)d_in[5];
    const float* eps   = (const float*)d_in[6];
    const float* W1    = (const float*)d_in[7];
    const float* b1    = (const float*)d_in[8];
    const float* bn1g  = (const float*)d_in[9];
    const float* bn1b  = (const float*)d_in[10];
    const float* W2    = (const float*)d_in[11];
    const float* b2    = (const float*)d_in[12];
    const float* bnAg  = (const float*)d_in[13];
    const float* bnAb  = (const float*)d_in[14];
    const float* bnGg  = (const float*)d_in[15];
    const float* bnGb  = (const float*)d_in[16];
    const float* Wp1   = (const float*)d_in[17];
    const float* bp1   = (const float*)d_in[18];
    const float* Wp2   = (const float*)d_in[19];
    const float* bp2   = (const float*)d_in[20];
    const int* src_g   = (const int*)d_in[21];
    const int* dst_g   = (const int*)d_in[22];
    const int* gid_g   = (const int*)d_in[23];
    const int* src_q   = (const int*)d_in[24];
    const int* dst_q   = (const int*)d_in[25];
    const int* gid_q   = (const int*)d_in[26];

    int NG_ = in_sizes[0] / 128;
    int NQ_ = in_sizes[2] / 128;
    int EG_ = in_sizes[21];
    int EQ_ = in_sizes[24];

    float *H, *T0, *T1, *stats, *scale, *shift, *rd;
    cudaGetSymbolAddress((void**)&H,     g_H);
    cudaGetSymbolAddress((void**)&T0,    g_T0);
    cudaGetSymbolAddress((void**)&T1,    g_T1);
    cudaGetSymbolAddress((void**)&stats, g_stats);
    cudaGetSymbolAddress((void**)&scale, g_scale);
    cudaGetSymbolAddress((void**)&shift, g_shift);
    cudaGetSymbolAddress((void**)&rd,    g_read);

    zero_kernel<<<2, 256>>>(stats, 2 * DH);
    zero_kernel<<<(2 * NGR * DH + 255) / 256, 256>>>(rd, 2 * NGR * DH);

    process_graph(X,  src_g, dst_g, gid_g, NG_, EG_,
                  W_emb, b_emb, eps, W1, b1, bn1g, bn1b, W2, b2,
                  bnAg, bnAb, bnGg, bnGb, H, T0, T1, stats, scale, shift, rd);
    process_graph(Xq, src_q, dst_q, gid_q, NQ_, EQ_,
                  W_emb, b_emb, eps, W1, b1, bn1g, bn1b, W2, b2,
                  bnAg, bnAb, bnGg, bnGb, H, T0, T1, stats, scale, shift, rd + NGR * DH);

    predictor_k<<<NGR, DH>>>(rd, Wp1, bp1, Wp2, bp2, (float*)d_out);
}

// round 2
// speedup vs baseline: 1.0924x; 1.0924x over previous
#include <cuda_runtime.h>
#include <cstdint>

#define DH    256
#define NLAY  4
#define NGR   64
#define NGMAX 50000
#define BNEPS 1e-5f

// ---------------- scratch (static __device__ globals; no allocations) ----------------
__device__ float g_H [NGMAX*DH];
__device__ float g_T0[NGMAX*DH];
__device__ float g_T1[NGMAX*DH];
__device__ float g_stats[2*DH];
__device__ float g_scale[DH];
__device__ float g_shift[DH];
__device__ float g_read[2*NGR*DH];

// ---------------- small utility kernels ----------------
__global__ void zero_kernel(float* p, int n) {
    int i = blockIdx.x * blockDim.x + threadIdx.x;
    if (i < n) p[i] = 0.f;
}

// ================= tensor-core GEMM (split-TF32, ~fp32 accurate) =================
// C = op_A(A) @ W + bias,  A:[M,K] row-major, W:[K,256] row-major, C:[M,256]
// TRANS_A: a = relu(a*scale[k]+shift[k]) fused into the A-tile load
// stats:   per-column sum/sumsq of C accumulated atomically (for following BN)
//
// Block tile 128x128, BK=16, 256 threads (8 warps, each 64x32 = 4x4 m16n8k8 frags).
// Split: hi = tf32(x), lo = tf32(x - hi);  D += Ah*Bh + Ah*Bl + Al*Bh.

__device__ __forceinline__ uint32_t f2tf32(float x) {
    uint32_t r; asm("cvt.rna.tf32.f32 %0, %1;" : "=r"(r) : "f"(x)); return r;
}
__device__ __forceinline__ void mma_tf32(float* d, const uint32_t* a, const uint32_t* b) {
    asm volatile("mma.sync.aligned.m16n8k8.row.col.f32.tf32.tf32.f32 "
        "{%0,%1,%2,%3}, {%4,%5,%6,%7}, {%8,%9}, {%0,%1,%2,%3};\n"
        : "+f"(d[0]), "+f"(d[1]), "+f"(d[2]), "+f"(d[3])
        : "r"(a[0]), "r"(a[1]), "r"(a[2]), "r"(a[3]), "r"(b[0]), "r"(b[1]));
}

#define TG_SMEM_BYTES 58368   // AsH/AsL: 128*40*4*2 = 40960 ; BsH/BsL: 16*136*4*2 = 17408

template<int K, bool TRANS_A>
__global__ __launch_bounds__(256) void tgemm_k(
    const float* __restrict__ A, const float* __restrict__ W,
    const float* __restrict__ bias, float* __restrict__ C, int M,
    const float* __restrict__ scA, const float* __restrict__ shA,
    float* __restrict__ stats)
{
    extern __shared__ uint32_t sm[];
    uint32_t (*AsH)[40]  = (uint32_t(*)[40]) (sm);
    uint32_t (*AsL)[40]  = (uint32_t(*)[40]) (sm + 5120);
    uint32_t (*BsH)[136] = (uint32_t(*)[136])(sm + 10240);
    uint32_t (*BsL)[136] = (uint32_t(*)[136])(sm + 12416);

    const int tid  = threadIdx.x;
    const int wid  = tid >> 5, lane = tid & 31;
    const int g    = lane >> 2, tig = lane & 3;
    const int mrw  = (wid & 1) * 64;     // warp M offset in tile
    const int nbw  = (wid >> 1) * 32;    // warp N offset in tile
    const int mbase = blockIdx.x * 128;
    const int nbase = blockIdx.y * 128;

    float acc[4][4][4] = {};

    const int ar  = tid >> 2;            // A loader: row 0..63 (+64)
    const int ac0 = (tid & 3) * 4;       // A loader: col base {0,4,8,12}
    const int abase_p = (ac0 & 8) | ((ac0 >> 2) & 1);  // permuted k-col base
    const int bk  = tid >> 4;            // B loader: k row 0..15
    const int bn0 = (tid & 15) * 4;      // B loader: n base (+64)

    for (int kt = 0; kt < K; kt += 16) {
        // ---- stage A tile (with optional fused BN+ReLU), split hi/lo ----
        #pragma unroll
        for (int i = 0; i < 2; i++) {
            int rl = ar + i * 64;
            int r  = mbase + rl;
            float4 v = make_float4(0.f, 0.f, 0.f, 0.f);
            if (r < M) v = *(const float4*)&A[(long)r * K + kt + ac0];
            float vv[4] = {v.x, v.y, v.z, v.w};
            #pragma unroll
            for (int j = 0; j < 4; j++) {
                float x = vv[j];
                if (TRANS_A) {
                    int kg = kt + ac0 + j;
                    x = fmaxf(fmaf(x, __ldg(&scA[kg]), __ldg(&shA[kg])), 0.f);
                }
                uint32_t h = f2tf32(x);
                uint32_t l = f2tf32(x - __uint_as_float(h));
                AsH[rl][abase_p + 2 * j] = h;
                AsL[rl][abase_p + 2 * j] = l;
            }
        }
        // ---- stage B tile, split hi/lo ----
        #pragma unroll
        for (int i = 0; i < 2; i++) {
            int n0 = bn0 + i * 64;
            float4 w = *(const float4*)&W[(long)(kt + bk) * DH + nbase + n0];
            float ww[4] = {w.x, w.y, w.z, w.w};
            uint4 h4, l4;
            h4.x = f2tf32(ww[0]); l4.x = f2tf32(ww[0] - __uint_as_float(h4.x));
            h4.y = f2tf32(ww[1]); l4.y = f2tf32(ww[1] - __uint_as_float(h4.y));
            h4.z = f2tf32(ww[2]); l4.z = f2tf32(ww[2] - __uint_as_float(h4.z));
            h4.w = f2tf32(ww[3]); l4.w = f2tf32(ww[3] - __uint_as_float(h4.w));
            *(uint4*)&BsH[bk][n0] = h4;
            *(uint4*)&BsL[bk][n0] = l4;
        }
        __syncthreads();

        #pragma unroll
        for (int kb = 0; kb < 16; kb += 8) {
            uint32_t ah[4][4], al_[4][4], bh[4][2], bl[4][2];
            #pragma unroll
            for (int mf = 0; mf < 4; mf++) {
                int r0 = mrw + mf * 16 + g;
                uint2 h0 = *(const uint2*)&AsH[r0    ][kb + tig * 2];
                uint2 h1 = *(const uint2*)&AsH[r0 + 8][kb + tig * 2];
                uint2 l0 = *(const uint2*)&AsL[r0    ][kb + tig * 2];
                uint2 l1 = *(const uint2*)&AsL[r0 + 8][kb + tig * 2];
                ah[mf][0] = h0.x; ah[mf][2] = h0.y; ah[mf][1] = h1.x; ah[mf][3] = h1.y;
                al_[mf][0] = l0.x; al_[mf][2] = l0.y; al_[mf][1] = l1.x; al_[mf][3] = l1.y;
            }
            #pragma unroll
            for (int nf = 0; nf < 4; nf++) {
                int c = nbw + nf * 8 + g;
                bh[nf][0] = BsH[kb + tig][c];  bh[nf][1] = BsH[kb + tig + 4][c];
                bl[nf][0] = BsL[kb + tig][c];  bl[nf][1] = BsL[kb + tig + 4][c];
            }
            #pragma unroll
            for (int mf = 0; mf < 4; mf++)
                #pragma unroll
                for (int nf = 0; nf < 4; nf++) {
                    mma_tf32(acc[mf][nf], ah[mf],  bh[nf]);
                    mma_tf32(acc[mf][nf], ah[mf],  bl[nf]);
                    mma_tf32(acc[mf][nf], al_[mf], bh[nf]);
                }
        }
        __syncthreads();
    }

    // ---- epilogue: bias, store, column stats ----
    float s[4][2] = {}, q[4][2] = {};
    #pragma unroll
    for (int nf = 0; nf < 4; nf++) {
        int col = nbase + nbw + nf * 8 + 2 * tig;
        float2 bb = *(const float2*)&bias[col];
        #pragma unroll
        for (int mf = 0; mf < 4; mf++) {
            int r0 = mbase + mrw + mf * 16 + g;
            float v0 = acc[mf][nf][0] + bb.x, v1 = acc[mf][nf][1] + bb.y;
            float v2 = acc[mf][nf][2] + bb.x, v3 = acc[mf][nf][3] + bb.y;
            if (r0 < M) {
                float2 o = {v0, v1};
                *(float2*)&C[(long)r0 * DH + col] = o;
                s[nf][0] += v0; s[nf][1] += v1;
                q[nf][0] += v0 * v0; q[nf][1] += v1 * v1;
            }
            if (r0 + 8 < M) {
                float2 o = {v2, v3};
                *(float2*)&C[(long)(r0 + 8) * DH + col] = o;
                s[nf][0] += v2; s[nf][1] += v3;
                q[nf][0] += v2 * v2; q[nf][1] += v3 * v3;
            }
        }
    }
    if (stats) {
        #pragma unroll
        for (int nf = 0; nf < 4; nf++)
            #pragma unroll
            for (int c2 = 0; c2 < 2; c2++) {
                float ss = s[nf][c2], qq = q[nf][c2];
                ss += __shfl_xor_sync(0xffffffffu, ss, 4);
                ss += __shfl_xor_sync(0xffffffffu, ss, 8);
                ss += __shfl_xor_sync(0xffffffffu, ss, 16);
                qq += __shfl_xor_sync(0xffffffffu, qq, 4);
                qq += __shfl_xor_sync(0xffffffffu, qq, 8);
                qq += __shfl_xor_sync(0xffffffffu, qq, 16);
                if (lane < 4) {
                    int col = nbase + nbw + nf * 8 + 2 * tig + c2;
                    atomicAdd(&stats[col], ss);
                    atomicAdd(&stats[DH + col], qq);
                }
            }
    }
}

// ---------------- BN finalize: stats -> (scale, shift); zero stats for reuse ----------------
__global__ void bn_finalize_k(const float* __restrict__ gamma, const float* __restrict__ beta,
                              float invN, float* stats, float* scale, float* shift) {
    int t = threadIdx.x;
    float m  = stats[t] * invN;
    float v  = stats[DH + t] * invN - m * m;
    float sc = gamma[t] * rsqrtf(v + BNEPS);
    scale[t] = sc;
    shift[t] = fmaf(-m, sc, beta[t]);
    stats[t] = 0.f; stats[DH + t] = 0.f;
}

// ---------------- aggregation ----------------
__global__ void init_agg_k(const float* __restrict__ H, float* __restrict__ out,
                           const float* __restrict__ eps, int l, int n4) {
    float e = 1.f + eps[l];
    int stride = gridDim.x * blockDim.x;
    for (int i = blockIdx.x * blockDim.x + threadIdx.x; i < n4; i += stride) {
        float4 v = ((const float4*)H)[i];
        v.x *= e; v.y *= e; v.z *= e; v.w *= e;
        ((float4*)out)[i] = v;
    }
}

__device__ __forceinline__ void red_add_v4(float* p, float4 v) {
    asm volatile("red.global.add.v4.f32 [%0], {%1,%2,%3,%4};"
                 :: "l"(p), "f"(v.x), "f"(v.y), "f"(v.z), "f"(v.w) : "memory");
}

// one warp per edge: out[dst] += H[src]
__global__ __launch_bounds__(256) void scatter_k(
    const float* __restrict__ H, float* __restrict__ out,
    const int* __restrict__ src, const int* __restrict__ dst, int E)
{
    int w    = (blockIdx.x * blockDim.x + threadIdx.x) >> 5;
    int lane = threadIdx.x & 31;
    if (w >= E) return;
    int s = src[w], d = dst[w];
    const float4* hs = (const float4*)(H + (long)s * DH);
    float* od = out + (long)d * DH;
    float4 a = hs[lane * 2];
    float4 b = hs[lane * 2 + 1];
    red_add_v4(od + lane * 8,     a);
    red_add_v4(od + lane * 8 + 4, b);
}

// ---------------- elementwise BN stages ----------------
__global__ void bnrelu_stats_k(const float* __restrict__ X, float* __restrict__ Y,
                               const float* __restrict__ scale, const float* __restrict__ shift,
                               int M, float* stats) {
    int c = threadIdx.x;
    float sc = scale[c], sh = shift[c];
    int rpb = (M + gridDim.x - 1) / gridDim.x;
    int r0 = blockIdx.x * rpb;
    int r1 = min(M, r0 + rpb);
    float s = 0.f, q = 0.f;
    for (int r = r0; r < r1; r++) {
        float v = fmaxf(fmaf(X[(long)r * DH + c], sc, sh), 0.f);
        Y[(long)r * DH + c] = v;
        s += v; q += v * v;
    }
    atomicAdd(&stats[c], s);
    atomicAdd(&stats[DH + c], q);
}

__global__ void bnrelu_resid_k(const float* __restrict__ X, float* __restrict__ H,
                               const float* __restrict__ scale, const float* __restrict__ shift,
                               int M) {
    int c = threadIdx.x;
    float sc = scale[c], sh = shift[c];
    int rpb = (M + gridDim.x - 1) / gridDim.x;
    int r0 = blockIdx.x * rpb;
    int r1 = min(M, r0 + rpb);
    for (int r = r0; r < r1; r++) {
        long idx = (long)r * DH + c;
        H[idx] += fmaxf(fmaf(X[idx], sc, sh), 0.f);
    }
}

// ---------------- readout ----------------
__global__ void readout_k(const float* __restrict__ H, const int* __restrict__ gid,
                          float* __restrict__ out, int M) {
    int c  = threadIdx.x;
    int r0 = blockIdx.x * 64;
    if (r0 >= M) return;
    int r1 = min(M, r0 + 64);
    int cur = gid[r0];
    float acc = 0.f;
    for (int r = r0; r < r1; r++) {
        int g = gid[r];
        if (g != cur) { atomicAdd(&out[cur * DH + c], acc); acc = 0.f; cur = g; }
        acc += H[(long)r * DH + c];
    }
    atomicAdd(&out[cur * DH + c], acc);
}

// ---------------- final predictor ----------------
__global__ void predictor_k(const float* __restrict__ rd, const float* __restrict__ Wp1,
                            const float* __restrict__ bp1, const float* __restrict__ Wp2,
                            const float* __restrict__ bp2, float* __restrict__ out) {
    __shared__ float dvec[DH];
    __shared__ float hred[DH];
    int g = blockIdx.x, t = threadIdx.x;
    dvec[t] = fabsf(rd[g * DH + t] - rd[NGR * DH + g * DH + t]);
    __syncthreads();
    float acc = bp1[t];
    for (int k = 0; k < DH; k++) acc = fmaf(dvec[k], Wp1[k * DH + t], acc);
    hred[t] = fmaxf(acc, 0.f) * Wp2[t];
    __syncthreads();
    for (int s = DH / 2; s > 0; s >>= 1) {
        if (t < s) hred[t] += hred[t + s];
        __syncthreads();
    }
    if (t == 0) out[g] = hred[0] + bp2[0];
}

// ---------------- host-side pipeline ----------------
static void process_graph(const float* X, const int* src, const int* dst, const int* gid,
                          int N, int E,
                          const float* W_emb, const float* b_emb, const float* eps,
                          const float* W1, const float* b1, const float* g1, const float* be1,
                          const float* W2, const float* b2, const float* gA, const float* beA,
                          const float* gG, const float* beG,
                          float* H, float* T0, float* T1,
                          float* stats, float* scale, float* shift, float* readout)
{
    dim3 gg((N + 127) / 128, 2);
    // node embedding
    tgemm_k<128, false><<<gg, 256, TG_SMEM_BYTES>>>(X, W_emb, b_emb, H, N,
                                                    nullptr, nullptr, nullptr);
    float invN = 1.f / (float)N;
    for (int l = 0; l < NLAY; l++) {
        init_agg_k<<<1024, 256>>>(H, T0, eps, l, N * DH / 4);
        scatter_k<<<(E + 7) / 8, 256>>>(H, T0, src, dst, E);
        tgemm_k<256, false><<<gg, 256, TG_SMEM_BYTES>>>(T0, W1 + l * DH * DH, b1 + l * DH,
                                                        T1, N, nullptr, nullptr, stats);
        bn_finalize_k<<<1, DH>>>(g1 + l * DH, be1 + l * DH, invN, stats, scale, shift);
        tgemm_k<256, true><<<gg, 256, TG_SMEM_BYTES>>>(T1, W2 + l * DH * DH, b2 + l * DH,
                                                       T0, N, scale, shift, stats);
        bn_finalize_k<<<1, DH>>>(gA + l * DH, beA + l * DH, invN, stats, scale, shift);
        bnrelu_stats_k<<<512, DH>>>(T0, T1, scale, shift, N, stats);
        bn_finalize_k<<<1, DH>>>(gG + l * DH, beG + l * DH, invN, stats, scale, shift);
        bnrelu_resid_k<<<512, DH>>>(T1, H, scale, shift, N);
    }
    readout_k<<<(N + 63) / 64, 256>>>(H, gid, readout, N);
}

extern "C" void kernel_launch(void* const* d_in, const int* in_sizes, int n_in,
                              void* d_out, int out_size) {
    const float* X     = (const float*)d_in[0];
    const float* Xq    = (const float*)d_in[2];
    const float* W_emb = (const float*)d_in[4];
    const float* b_emb = (const float*)d_in[5];
    const float* eps   = (const float*)d_in[6];
    const float* W1    = (const float*)d_in[7];
    const float* b1    = (const float*)d_in[8];
    const float* bn1g  = (const float*)d_in[9];
    const float* bn1b  = (const float*)d_in[10];
    const float* W2    = (const float*)d_in[11];
    const float* b2    = (const float*)d_in[12];
    const float* bnAg  = (const float*)d_in[13];
    const float* bnAb  = (const float*)d_in[14];
    const float* bnGg  = (const float*)d_in[15];
    const float* bnGb  = (const float*)d_in[16];
    const float* Wp1   = (const float*)d_in[17];
    const float* bp1   = (const float*)d_in[18];
    const float* Wp2   = (const float*)d_in[19];
    const float* bp2   = (const float*)d_in[20];
    const int* src_g   = (const int*)d_in[21];
    const int* dst_g   = (const int*)d_in[22];
    const int* gid_g   = (const int*)d_in[23];
    const int* src_q   = (const int*)d_in[24];
    const int* dst_q   = (const int*)d_in[25];
    const int* gid_q   = (const int*)d_in[26];

    int NG_ = in_sizes[0] / 128;
    int NQ_ = in_sizes[2] / 128;
    int EG_ = in_sizes[21];
    int EQ_ = in_sizes[24];

    cudaFuncSetAttribute(tgemm_k<128, false>, cudaFuncAttributeMaxDynamicSharedMemorySize, TG_SMEM_BYTES);
    cudaFuncSetAttribute(tgemm_k<256, false>, cudaFuncAttributeMaxDynamicSharedMemorySize, TG_SMEM_BYTES);
    cudaFuncSetAttribute(tgemm_k<256, true>,  cudaFuncAttributeMaxDynamicSharedMemorySize, TG_SMEM_BYTES);

    float *H, *T0, *T1, *stats, *scale, *shift, *rd;
    cudaGetSymbolAddress((void**)&H,     g_H);
    cudaGetSymbolAddress((void**)&T0,    g_T0);
    cudaGetSymbolAddress((void**)&T1,    g_T1);
    cudaGetSymbolAddress((void**)&stats, g_stats);
    cudaGetSymbolAddress((void**)&scale, g_scale);
    cudaGetSymbolAddress((void**)&shift, g_shift);
    cudaGetSymbolAddress((void**)&rd,    g_read);

    zero_kernel<<<2, 256>>>(stats, 2 * DH);
    zero_kernel<<<(2 * NGR * DH + 255) / 256, 256>>>(rd, 2 * NGR * DH);

    process_graph(X,  src_g, dst_g, gid_g, NG_, EG_,
                  W_emb, b_emb, eps, W1, b1, bn1g, bn1b, W2, b2,
                  bnAg, bnAb, bnGg, bnGb, H, T0, T1, stats, scale, shift, rd);
    process_graph(Xq, src_q, dst_q, gid_q, NQ_, EQ_,
                  W_emb, b_emb, eps, W1, b1, bn1g, bn1b, W2, b2,
                  bnAg, bnAb, bnGg, bnGb, H, T0, T1, stats, scale, shift, rd + NGR * DH);

    predictor_k<<<NGR, DH>>>(rd, Wp1, bp1, Wp2, bp2, (float*)d_out);
}

// round 3
// speedup vs baseline: 1.8363x; 1.6809x over previous
#include <cuda_runtime.h>
#include <cuda_bf16.h>
#include <cstdint>

#define DH    256
#define NLAY  4
#define NGR   64
#define NGMAX 50000
#define EMAX  800000
#define BNEPS 1e-5f

// ---------------- scratch (static __device__ globals; no allocations) ----------------
__device__ float g_H [NGMAX*DH];
__device__ float g_T0[NGMAX*DH];
__device__ float g_T1[NGMAX*DH];
__device__ float g_stats[2*DH];
__device__ float g_scale[DH];
__device__ float g_shift[DH];
__device__ float g_read[2*NGR*DH];
__device__ int   g_cnt [NGMAX];
__device__ int   g_wofs[NGMAX];
__device__ int   g_rowptr[NGMAX+1];
__device__ int   g_esrc[EMAX];

// ---------------- small utility kernels ----------------
__global__ void zero_kernel(float* p, int n) {
    int i = blockIdx.x * blockDim.x + threadIdx.x;
    if (i < n) p[i] = 0.f;
}
__global__ void zeroi_kernel(int* p, int n) {
    int i = blockIdx.x * blockDim.x + threadIdx.x;
    if (i < n) p[i] = 0;
}

// ================= CSR build (by dst) =================
__global__ void hist_k(const int* __restrict__ dst, int E, int* __restrict__ cnt) {
    int i = blockIdx.x * blockDim.x + threadIdx.x;
    if (i < E) atomicAdd(&cnt[dst[i]], 1);
}

__global__ void scan_k(const int* __restrict__ cnt, int* __restrict__ rowptr,
                       int* __restrict__ wofs, int N, int E) {
    __shared__ int part[1024];
    int t = threadIdx.x;
    int chunk = (N + 1023) >> 10;
    int b0 = t * chunk, b1 = min(N, b0 + chunk);
    int s = 0;
    for (int b = b0; b < b1; b++) s += cnt[b];
    part[t] = s;
    __syncthreads();
    for (int off = 1; off < 1024; off <<= 1) {
        int v = (t >= off) ? part[t - off] : 0;
        __syncthreads();
        part[t] += v;
        __syncthreads();
    }
    int run = t ? part[t - 1] : 0;
    for (int b = b0; b < b1; b++) {
        rowptr[b] = run; wofs[b] = run; run += cnt[b];
    }
    if (t == 1023) rowptr[N] = E;
}

__global__ void fill_k(const int* __restrict__ src, const int* __restrict__ dst, int E,
                       int* __restrict__ wofs, int* __restrict__ esrc) {
    int i = blockIdx.x * blockDim.x + threadIdx.x;
    if (i < E) {
        int p = atomicAdd(&wofs[dst[i]], 1);
        esrc[p] = src[i];
    }
}

// gather: T0[v] = (1+eps[l])*H[v] + sum_{e: dst=v} H[src[e]]   (one warp per node)
__global__ __launch_bounds__(256) void gather_k(
    const float* __restrict__ H, float* __restrict__ out,
    const int* __restrict__ rowptr, const int* __restrict__ esrc,
    const float* __restrict__ eps, int l, int N)
{
    int w    = (blockIdx.x * blockDim.x + threadIdx.x) >> 5;
    int lane = threadIdx.x & 31;
    if (w >= N) return;
    float e = 1.f + __ldg(&eps[l]);
    const float4* hr = (const float4*)(H + (long)w * DH);
    float4 a = hr[lane * 2], b = hr[lane * 2 + 1];
    a.x *= e; a.y *= e; a.z *= e; a.w *= e;
    b.x *= e; b.y *= e; b.z *= e; b.w *= e;
    int i0 = rowptr[w], i1 = rowptr[w + 1];
    for (int i = i0; i < i1; i++) {
        int s = __ldg(&esrc[i]);
        const float4* hs = (const float4*)(H + (long)s * DH);
        float4 u = hs[lane * 2], v = hs[lane * 2 + 1];
        a.x += u.x; a.y += u.y; a.z += u.z; a.w += u.w;
        b.x += v.x; b.y += v.y; b.z += v.z; b.w += v.w;
    }
    float4* o = (float4*)(out + (long)w * DH);
    o[lane * 2] = a; o[lane * 2 + 1] = b;
}

// ================= tensor-core GEMM (split-BF16 x3, ~fp32 accurate) =================
// C = op_A(A) @ W + bias,  A:[M,K] row-major, W:[K,256] row-major, C:[M,256]
// hi=bf16(x), lo=bf16(x-hi);  D += Ah*Bh + Ah*Bl + Al*Bh  via mma.m16n8k16.bf16
// Block tile 128x128, BK=32, 256 threads (8 warps, each 64x32).

__device__ __forceinline__ uint32_t pack_hi(float e, float o, float& re, float& ro) {
    __nv_bfloat16 he = __float2bfloat16(e);
    __nv_bfloat16 ho = __float2bfloat16(o);
    re = e - __bfloat162float(he);
    ro = o - __bfloat162float(ho);
    return (uint32_t)__bfloat16_as_ushort(he) | ((uint32_t)__bfloat16_as_ushort(ho) << 16);
}
__device__ __forceinline__ uint32_t pack_lo(float re, float ro) {
    __nv_bfloat16 le = __float2bfloat16(re);
    __nv_bfloat16 lo = __float2bfloat16(ro);
    return (uint32_t)__bfloat16_as_ushort(le) | ((uint32_t)__bfloat16_as_ushort(lo) << 16);
}
__device__ __forceinline__ void mma_bf16(float* d, const uint32_t* a, const uint32_t* b) {
    asm volatile("mma.sync.aligned.m16n8k16.row.col.f32.bf16.bf16.f32 "
        "{%0,%1,%2,%3}, {%4,%5,%6,%7}, {%8,%9}, {%0,%1,%2,%3};\n"
        : "+f"(d[0]), "+f"(d[1]), "+f"(d[2]), "+f"(d[3])
        : "r"(a[0]), "r"(a[1]), "r"(a[2]), "r"(a[3]), "r"(b[0]), "r"(b[1]));
}

template<int K, bool TRANS_A>
__global__ __launch_bounds__(256, 2) void tgemm_k(
    const float* __restrict__ A, const float* __restrict__ W,
    const float* __restrict__ bias, float* __restrict__ C, int M,
    const float* __restrict__ scA, const float* __restrict__ shA,
    float* __restrict__ stats)
{
    __shared__ uint32_t AH[128][20];   // 128 rows x 16 kpairs (+4 pad) -> conflict-free frags
    __shared__ uint32_t AL[128][20];
    __shared__ uint32_t BH[16][136];   // 16 kpairs x 128 n (+8 pad)
    __shared__ uint32_t BL[16][136];
    __shared__ float sSc[256], sSh[256];

    const int tid  = threadIdx.x;
    const int wid  = tid >> 5, lane = tid & 31;
    const int g    = lane >> 2, tig = lane & 3;
    const int mrw  = (wid & 1) * 64;
    const int nbw  = (wid >> 1) * 32;
    const int mbase = blockIdx.x * 128;
    const int nbase = blockIdx.y * 128;

    if (TRANS_A) {
        if (tid < K) { sSc[tid] = scA[tid]; sSh[tid] = shA[tid]; }
        __syncthreads();
    }

    float acc[4][4][4] = {};

    const int ar  = tid >> 1;          // A loader row 0..127
    const int akc = (tid & 1) * 16;    // A loader k base (0 / 16)
    const int bkp = tid >> 4;          // B loader kpair 0..15
    const int bn0 = (tid & 15) * 8;    // B loader n base

    for (int kt = 0; kt < K; kt += 32) {
        // ---- stage A (optional fused BN+ReLU), split hi/lo ----
        {
            int r = mbase + ar;
            #pragma unroll
            for (int j = 0; j < 4; j++) {
                int kc = akc + j * 4;
                float4 v = make_float4(0.f, 0.f, 0.f, 0.f);
                if (r < M) v = *(const float4*)&A[(long)r * K + kt + kc];
                float x0 = v.x, x1 = v.y, x2 = v.z, x3 = v.w;
                if (TRANS_A) {
                    x0 = fmaxf(fmaf(x0, sSc[kt + kc    ], sSh[kt + kc    ]), 0.f);
                    x1 = fmaxf(fmaf(x1, sSc[kt + kc + 1], sSh[kt + kc + 1]), 0.f);
                    x2 = fmaxf(fmaf(x2, sSc[kt + kc + 2], sSh[kt + kc + 2]), 0.f);
                    x3 = fmaxf(fmaf(x3, sSc[kt + kc + 3], sSh[kt + kc + 3]), 0.f);
                }
                float r0e, r0o, r1e, r1o;
                uint32_t h0 = pack_hi(x0, x1, r0e, r0o);
                uint32_t h1 = pack_hi(x2, x3, r1e, r1o);
                int kp = (kc >> 1);
                AH[ar][kp] = h0;  AH[ar][kp + 1] = h1;
                AL[ar][kp] = pack_lo(r0e, r0o);
                AL[ar][kp + 1] = pack_lo(r1e, r1o);
            }
        }
        // ---- stage B, split hi/lo ----
        {
            const float* We = &W[(long)(kt + 2 * bkp) * DH + nbase + bn0];
            const float* Wo = We + DH;
            #pragma unroll
            for (int j = 0; j < 2; j++) {
                float4 e4 = *(const float4*)(We + j * 4);
                float4 o4 = *(const float4*)(Wo + j * 4);
                float re, ro;
                uint4 h4, l4;
                h4.x = pack_hi(e4.x, o4.x, re, ro); l4.x = pack_lo(re, ro);
                h4.y = pack_hi(e4.y, o4.y, re, ro); l4.y = pack_lo(re, ro);
                h4.z = pack_hi(e4.z, o4.z, re, ro); l4.z = pack_lo(re, ro);
                h4.w = pack_hi(e4.w, o4.w, re, ro); l4.w = pack_lo(re, ro);
                *(uint4*)&BH[bkp][bn0 + j * 4] = h4;
                *(uint4*)&BL[bkp][bn0 + j * 4] = l4;
            }
        }
        __syncthreads();

        #pragma unroll
        for (int c = 0; c < 2; c++) {           // two k16 chunks per BK=32 tile
            uint32_t bh[4][2], bl[4][2];
            #pragma unroll
            for (int nf = 0; nf < 4; nf++) {
                int cn = nbw + nf * 8 + g;
                bh[nf][0] = BH[c * 8 + tig][cn];
                bh[nf][1] = BH[c * 8 + tig + 4][cn];
                bl[nf][0] = BL[c * 8 + tig][cn];
                bl[nf][1] = BL[c * 8 + tig + 4][cn];
            }
            #pragma unroll
            for (int mf = 0; mf < 4; mf++) {
                int r0 = mrw + mf * 16 + g;
                uint32_t ah[4], al_[4];
                ah[0] = AH[r0][c * 8 + tig];      ah[1] = AH[r0 + 8][c * 8 + tig];
                ah[2] = AH[r0][c * 8 + tig + 4];  ah[3] = AH[r0 + 8][c * 8 + tig + 4];
                al_[0] = AL[r0][c * 8 + tig];     al_[1] = AL[r0 + 8][c * 8 + tig];
                al_[2] = AL[r0][c * 8 + tig + 4]; al_[3] = AL[r0 + 8][c * 8 + tig + 4];
                #pragma unroll
                for (int nf = 0; nf < 4; nf++) {
                    mma_bf16(acc[mf][nf], ah,  bh[nf]);
                    mma_bf16(acc[mf][nf], ah,  bl[nf]);
                    mma_bf16(acc[mf][nf], al_, bh[nf]);
                }
            }
        }
        __syncthreads();
    }

    // ---- epilogue: bias, store, column stats ----
    float s[4][2] = {}, q[4][2] = {};
    #pragma unroll
    for (int nf = 0; nf < 4; nf++) {
        int col = nbase + nbw + nf * 8 + 2 * tig;
        float2 bb = *(const float2*)&bias[col];
        #pragma unroll
        for (int mf = 0; mf < 4; mf++) {
            int r0 = mbase + mrw + mf * 16 + g;
            float v0 = acc[mf][nf][0] + bb.x, v1 = acc[mf][nf][1] + bb.y;
            float v2 = acc[mf][nf][2] + bb.x, v3 = acc[mf][nf][3] + bb.y;
            if (r0 < M) {
                float2 o = {v0, v1};
                *(float2*)&C[(long)r0 * DH + col] = o;
                s[nf][0] += v0; s[nf][1] += v1;
                q[nf][0] += v0 * v0; q[nf][1] += v1 * v1;
            }
            if (r0 + 8 < M) {
                float2 o = {v2, v3};
                *(float2*)&C[(long)(r0 + 8) * DH + col] = o;
                s[nf][0] += v2; s[nf][1] += v3;
                q[nf][0] += v2 * v2; q[nf][1] += v3 * v3;
            }
        }
    }
    if (stats) {
        #pragma unroll
        for (int nf = 0; nf < 4; nf++)
            #pragma unroll
            for (int c2 = 0; c2 < 2; c2++) {
                float ss = s[nf][c2], qq = q[nf][c2];
                ss += __shfl_xor_sync(0xffffffffu, ss, 4);
                ss += __shfl_xor_sync(0xffffffffu, ss, 8);
                ss += __shfl_xor_sync(0xffffffffu, ss, 16);
                qq += __shfl_xor_sync(0xffffffffu, qq, 4);
                qq += __shfl_xor_sync(0xffffffffu, qq, 8);
                qq += __shfl_xor_sync(0xffffffffu, qq, 16);
                if (lane < 4) {
                    int col = nbase + nbw + nf * 8 + 2 * tig + c2;
                    atomicAdd(&stats[col], ss);
                    atomicAdd(&stats[DH + col], qq);
                }
            }
    }
}

// ---------------- BN finalize ----------------
__global__ void bn_finalize_k(const float* __restrict__ gamma, const float* __restrict__ beta,
                              float invN, float* stats, float* scale, float* shift) {
    int t = threadIdx.x;
    float m  = stats[t] * invN;
    float v  = stats[DH + t] * invN - m * m;
    float sc = gamma[t] * rsqrtf(v + BNEPS);
    scale[t] = sc;
    shift[t] = fmaf(-m, sc, beta[t]);
    stats[t] = 0.f; stats[DH + t] = 0.f;
}

// ---------------- elementwise BN stages ----------------
__global__ void bnrelu_stats_k(const float* __restrict__ X, float* __restrict__ Y,
                               const float* __restrict__ scale, const float* __restrict__ shift,
                               int M, float* stats) {
    int c = threadIdx.x;
    float sc = scale[c], sh = shift[c];
    int rpb = (M + gridDim.x - 1) / gridDim.x;
    int r0 = blockIdx.x * rpb;
    int r1 = min(M, r0 + rpb);
    float s = 0.f, q = 0.f;
    for (int r = r0; r < r1; r++) {
        float v = fmaxf(fmaf(X[(long)r * DH + c], sc, sh), 0.f);
        Y[(long)r * DH + c] = v;
        s += v; q += v * v;
    }
    atomicAdd(&stats[c], s);
    atomicAdd(&stats[DH + c], q);
}

__global__ void bnrelu_resid_k(const float* __restrict__ X, float* __restrict__ H,
                               const float* __restrict__ scale, const float* __restrict__ shift,
                               int M) {
    int c = threadIdx.x;
    float sc = scale[c], sh = shift[c];
    int rpb = (M + gridDim.x - 1) / gridDim.x;
    int r0 = blockIdx.x * rpb;
    int r1 = min(M, r0 + rpb);
    for (int r = r0; r < r1; r++) {
        long idx = (long)r * DH + c;
        H[idx] += fmaxf(fmaf(X[idx], sc, sh), 0.f);
    }
}

// ---------------- readout ----------------
__global__ void readout_k(const float* __restrict__ H, const int* __restrict__ gid,
                          float* __restrict__ out, int M) {
    int c  = threadIdx.x;
    int r0 = blockIdx.x * 64;
    if (r0 >= M) return;
    int r1 = min(M, r0 + 64);
    int cur = gid[r0];
    float acc = 0.f;
    for (int r = r0; r < r1; r++) {
        int g = gid[r];
        if (g != cur) { atomicAdd(&out[cur * DH + c], acc); acc = 0.f; cur = g; }
        acc += H[(long)r * DH + c];
    }
    atomicAdd(&out[cur * DH + c], acc);
}

// ---------------- final predictor ----------------
__global__ void predictor_k(const float* __restrict__ rd, const float* __restrict__ Wp1,
                            const float* __restrict__ bp1, const float* __restrict__ Wp2,
                            const float* __restrict__ bp2, float* __restrict__ out) {
    __shared__ float dvec[DH];
    __shared__ float hred[DH];
    int g = blockIdx.x, t = threadIdx.x;
    dvec[t] = fabsf(rd[g * DH + t] - rd[NGR * DH + g * DH + t]);
    __syncthreads();
    float acc = bp1[t];
    for (int k = 0; k < DH; k++) acc = fmaf(dvec[k], Wp1[k * DH + t], acc);
    hred[t] = fmaxf(acc, 0.f) * Wp2[t];
    __syncthreads();
    for (int s = DH / 2; s > 0; s >>= 1) {
        if (t < s) hred[t] += hred[t + s];
        __syncthreads();
    }
    if (t == 0) out[g] = hred[0] + bp2[0];
}

// ---------------- host-side pipeline ----------------
static void process_graph(const float* X, const int* src, const int* dst, const int* gid,
                          int N, int E,
                          const float* W_emb, const float* b_emb, const float* eps,
                          const float* W1, const float* b1, const float* g1, const float* be1,
                          const float* W2, const float* b2, const float* gA, const float* beA,
                          const float* gG, const float* beG,
                          float* H, float* T0, float* T1,
                          float* stats, float* scale, float* shift, float* readout,
                          int* cnt, int* wofs, int* rowptr, int* esrc)
{
    // ---- build CSR by dst (reused across layers) ----
    zeroi_kernel<<<(N + 255) / 256, 256>>>(cnt, N);
    hist_k<<<(E + 255) / 256, 256>>>(dst, E, cnt);
    scan_k<<<1, 1024>>>(cnt, rowptr, wofs, N, E);
    fill_k<<<(E + 255) / 256, 256>>>(src, dst, E, wofs, esrc);

    dim3 gg((N + 127) / 128, 2);
    tgemm_k<128, false><<<gg, 256>>>(X, W_emb, b_emb, H, N, nullptr, nullptr, nullptr);
    float invN = 1.f / (float)N;
    for (int l = 0; l < NLAY; l++) {
        gather_k<<<(N + 7) / 8, 256>>>(H, T0, rowptr, esrc, eps, l, N);
        tgemm_k<256, false><<<gg, 256>>>(T0, W1 + l * DH * DH, b1 + l * DH,
                                         T1, N, nullptr, nullptr, stats);
        bn_finalize_k<<<1, DH>>>(g1 + l * DH, be1 + l * DH, invN, stats, scale, shift);
        tgemm_k<256, true><<<gg, 256>>>(T1, W2 + l * DH * DH, b2 + l * DH,
                                        T0, N, scale, shift, stats);
        bn_finalize_k<<<1, DH>>>(gA + l * DH, beA + l * DH, invN, stats, scale, shift);
        bnrelu_stats_k<<<512, DH>>>(T0, T1, scale, shift, N, stats);
        bn_finalize_k<<<1, DH>>>(gG + l * DH, beG + l * DH, invN, stats, scale, shift);
        bnrelu_resid_k<<<512, DH>>>(T1, H, scale, shift, N);
    }
    readout_k<<<(N + 63) / 64, 256>>>(H, gid, readout, N);
}

extern "C" void kernel_launch(void* const* d_in, const int* in_sizes, int n_in,
                              void* d_out, int out_size) {
    const float* X     = (const float*)d_in[0];
    const float* Xq    = (const float*)d_in[2];
    const float* W_emb = (const float*)d_in[4];
    const float* b_emb = (const float*)d_in[5];
    const float* eps   = (const float*)d_in[6];
    const float* W1    = (const float*)d_in[7];
    const float* b1    = (const float*)d_in[8];
    const float* bn1g  = (const float*)d_in[9];
    const float* bn1b  = (const float*)d_in[10];
    const float* W2    = (const float*)d_in[11];
    const float* b2    = (const float*)d_in[12];
    const float* bnAg  = (const float*)d_in[13];
    const float* bnAb  = (const float*)d_in[14];
    const float* bnGg  = (const float*)d_in[15];
    const float* bnGb  = (const float*)d_in[16];
    const float* Wp1   = (const float*)d_in[17];
    const float* bp1   = (const float*)d_in[18];
    const float* Wp2   = (const float*)d_in[19];
    const float* bp2   = (const float*)d_in[20];
    const int* src_g   = (const int*)d_in[21];
    const int* dst_g   = (const int*)d_in[22];
    const int* gid_g   = (const int*)d_in[23];
    const int* src_q   = (const int*)d_in[24];
    const int* dst_q   = (const int*)d_in[25];
    const int* gid_q   = (const int*)d_in[26];

    int NG_ = in_sizes[0] / 128;
    int NQ_ = in_sizes[2] / 128;
    int EG_ = in_sizes[21];
    int EQ_ = in_sizes[24];

    float *H, *T0, *T1, *stats, *scale, *shift, *rd;
    int *cnt, *wofs, *rowptr, *esrc;
    cudaGetSymbolAddress((void**)&H,      g_H);
    cudaGetSymbolAddress((void**)&T0,     g_T0);
    cudaGetSymbolAddress((void**)&T1,     g_T1);
    cudaGetSymbolAddress((void**)&stats,  g_stats);
    cudaGetSymbolAddress((void**)&scale,  g_scale);
    cudaGetSymbolAddress((void**)&shift,  g_shift);
    cudaGetSymbolAddress((void**)&rd,     g_read);
    cudaGetSymbolAddress((void**)&cnt,    g_cnt);
    cudaGetSymbolAddress((void**)&wofs,   g_wofs);
    cudaGetSymbolAddress((void**)&rowptr, g_rowptr);
    cudaGetSymbolAddress((void**)&esrc,   g_esrc);

    zero_kernel<<<2, 256>>>(stats, 2 * DH);
    zero_kernel<<<(2 * NGR * DH + 255) / 256, 256>>>(rd, 2 * NGR * DH);

    process_graph(X,  src_g, dst_g, gid_g, NG_, EG_,
                  W_emb, b_emb, eps, W1, b1, bn1g, bn1b, W2, b2,
                  bnAg, bnAb, bnGg, bnGb, H, T0, T1, stats, scale, shift, rd,
                  cnt, wofs, rowptr, esrc);
    process_graph(Xq, src_q, dst_q, gid_q, NQ_, EQ_,
                  W_emb, b_emb, eps, W1, b1, bn1g, bn1b, W2, b2,
                  bnAg, bnAb, bnGg, bnGb, H, T0, T1, stats, scale, shift, rd + NGR * DH,
                  cnt, wofs, rowptr, esrc);

    predictor_k<<<NGR, DH>>>(rd, Wp1, bp1, Wp2, bp2, (float*)d_out);
}